// round 12
// baseline (speedup 1.0000x reference)
#include <cuda_runtime.h>
#include <math.h>

#define B 128
#define C 6
#define H 224
#define W 224
#define HWSZ (H*W)          // 50176
#define HW4 (HWSZ/4)        // 12544 float4 per channel
#define POOL 7
#define NS (POOL*POOL)      // 49
#define BC (B*C)            // 768
#define CS (C*NS)           // 294
#define FEAT (3*C)          // 18
#define W4 (W/4)            // 56 float4 per row
#define NT 512

__device__ float g_pooled[BC * NS];
__device__ unsigned int g_cnt[B];    // monotonically increasing ticket counters

__constant__ float c_prior[36] = {
    1.0f,  0.0f,  0.6f,  0.0f, -2.0f, 0.0f,
    0.0f,  1.0f,  0.6f,  0.0f,  0.0f, 0.0f,
    0.1f,  0.1f,  0.5f,  0.0f,  0.0f, 0.0f,
    0.0f,  0.0f,  0.0f,  1.0f,  0.0f, 0.0f,
    0.0f,  0.0f,  0.0f,  0.0f,  1.0f, 0.2f,
    0.0f, -0.6f, -0.6f, -0.6f,  0.6f, 1.0f
};
__constant__ float c_sign[6] = {1.f, -1.f, 1.f, -1.f, 1.f, 1.f};

__device__ __forceinline__ float tanh_f(float x) {
    float y;
    asm("tanh.approx.f32 %0, %1;" : "=f"(y) : "f"(x));
    return y;
}

// ---------------------------------------------------------------------------
// One fused kernel. Block = (batch b, concept d), 512 threads, 2 blocks/SM.
//  1. stats: stream own 200KB channel from DRAM (whole chip reads at once)
//  2. windows: gate (tanh) + 32x32 pool; L2 re-read (59MB resident < 126MB),
//     latency hidden by 16 warps x 8-deep unrolled loads (no reg prefetch)
//  3. ticket barrier on g_cnt[b] (monotonic, no reset kernel needed:
//     each replay adds exactly C; target = (ticket/C + 1)*C)
//  4. mixing + features + upsample: writes overlap other blocks' reads
// ---------------------------------------------------------------------------
__global__ __launch_bounds__(NT, 2)
void fused_kernel(const float* __restrict__ x,
                  const float* __restrict__ P_delta,
                  float* __restrict__ feat_out,
                  float* __restrict__ out)
{
    extern __shared__ float smem_pad[];            // occupancy pad (2/SM)
    __shared__ float ra[16], rb[16];
    __shared__ float s_sc, s_of;
    __shared__ float xs[CS], sal[CS], tmp[NS];
    __shared__ float Pcol[C], smean[C];
    __shared__ __align__(16) float g[52];
    __shared__ __align__(16) float4 hr4[POOL * W4];

    const int bc = blockIdx.x;
    const int b = bc / C, d = bc - b * C;
    const int tid = threadIdx.x;
    const int warp = tid >> 5, lane = tid & 31;
    const float* __restrict__ xc = x + (size_t)bc * HWSZ;

    // ---- phase 1: stats (24 float4/thread + tail, batches of 8) ----
    {
        const float4* __restrict__ xin = (const float4*)xc;
        float sum = 0.f, sq = 0.f;
        #pragma unroll
        for (int base = 0; base < 24; base += 8) {
            float4 v[8];
            #pragma unroll
            for (int k = 0; k < 8; ++k) v[k] = xin[(base + k) * NT + tid];
            #pragma unroll
            for (int k = 0; k < 8; ++k) {
                sum += (v[k].x + v[k].y) + (v[k].z + v[k].w);
                sq  += fmaf(v[k].x, v[k].x, fmaf(v[k].y, v[k].y,
                       fmaf(v[k].z, v[k].z, v[k].w * v[k].w)));
            }
        }
        if (tid < HW4 - 24 * NT) {                 // tail: 256 float4
            float4 v = xin[24 * NT + tid];
            sum += (v.x + v.y) + (v.z + v.w);
            sq  += fmaf(v.x, v.x, fmaf(v.y, v.y, fmaf(v.z, v.z, v.w * v.w)));
        }
        #pragma unroll
        for (int o = 16; o; o >>= 1) {
            sum += __shfl_down_sync(0xffffffffu, sum, o);
            sq  += __shfl_down_sync(0xffffffffu, sq,  o);
        }
        if (lane == 0) { ra[warp] = sum; rb[warp] = sq; }
        __syncthreads();
        if (warp == 0) {
            float s = (lane < 16) ? ra[lane] : 0.f;
            float q = (lane < 16) ? rb[lane] : 0.f;
            #pragma unroll
            for (int o = 8; o; o >>= 1) {
                s += __shfl_down_sync(0xffffffffu, s, o);
                q += __shfl_down_sync(0xffffffffu, q, o);
            }
            if (lane == 0) {
                const float invN = 1.0f / (float)HWSZ;
                float mean = s * invN;
                float var = fmaxf((q - s * s * invN)
                                  * (1.0f / (float)(HWSZ - 1)), 0.f);
                float is = 1.0f / (sqrtf(var) + 1e-5f);
                s_sc = is; s_of = -mean * is;
            }
        }
        __syncthreads();
    }
    const float sc = s_sc, of = s_of;

    // ---- phase 2: windows (16 warps, stride 16 covers all 49) ----
    {
        const int sub = lane >> 3, c4 = lane & 7;
        for (int win = warp; win < NS; win += 16) {
            const int py = win / POOL, px = win - py * POOL;
            const float4* __restrict__ base =
                (const float4*)(xc + (py * 32 + sub) * W + px * 32) + c4;
            float acc = 0.f;
            #pragma unroll
            for (int r = 0; r < 8; ++r) {          // rows sub, sub+4, ...
                float4 u = base[r * W];
                acc += tanh_f(fmaf(u.x, sc, of));
                acc += tanh_f(fmaf(u.y, sc, of));
                acc += tanh_f(fmaf(u.z, sc, of));
                acc += tanh_f(fmaf(u.w, sc, of));
            }
            #pragma unroll
            for (int o = 16; o; o >>= 1)
                acc += __shfl_down_sync(0xffffffffu, acc, o);
            if (lane == 0)
                g_pooled[bc * NS + win] = acc * (1.0f / 2048.0f) + 0.5f;
        }
    }
    __syncthreads();

    // ---- phase 3: ticket barrier (no reset needed; monotonic counter) ----
    if (tid == 0) {
        __threadfence();
        unsigned int ticket = atomicAdd(&g_cnt[b], 1u);
        unsigned int target = (ticket / C + 1u) * C;
        while (atomicAdd(&g_cnt[b], 0u) < target) __nanosleep(128);
    }
    __syncthreads();
    __threadfence();

    // ---- phase 4a: mixing ----
    if (tid < CS) xs[tid] = __ldcg(&g_pooled[b * CS + tid]);
    if (tid < C) Pcol[tid] = c_prior[tid * 6 + d] + 0.2f * tanhf(P_delta[tid * 6 + d]);
    __syncthreads();

    if (tid < C) {
        float m = 0.f;
        #pragma unroll
        for (int s = 0; s < NS; ++s) m += xs[tid * NS + s];
        smean[tid] = m * (1.0f / (float)NS);
    }
    __syncthreads();

    if (tid < CS) {
        const int cc = tid / NS;
        sal[tid] = fmaxf(c_sign[cc] * (xs[tid] - smean[cc]), 0.0f);
    }
    __syncthreads();

    if (tid < NS) {
        tmp[tid] = sal[tid]        * Pcol[0] + sal[NS + tid]   * Pcol[1]
                 + sal[2*NS + tid] * Pcol[2] + sal[3*NS + tid] * Pcol[3]
                 + sal[4*NS + tid] * Pcol[4] + sal[5*NS + tid] * Pcol[5];
    }
    __syncthreads();

    if (tid < NS) {
        const int ty = tid / POOL, tx = tid - ty * POOL;
        float acc = 0.f;
        int s = 0;
        #pragma unroll
        for (int sy = 0; sy < POOL; ++sy) {
            const float dy2 = (float)((sy - ty) * (sy - ty));
            #pragma unroll
            for (int sx = 0; sx < POOL; ++sx, ++s) {
                const float dx = (float)(sx - tx);
                acc += __expf(-(dy2 + dx * dx) * 0.78125f) * tmp[s];
            }
        }
        g[tid] = c_sign[d] * fmaxf(acc, 0.0f);
    }
    __syncthreads();

    // ---- phase 4b: features ----
    if (tid < 32) {
        float a  = g[tid];
        bool hi  = (tid + 32) < NS;
        float b2 = hi ? g[tid + 32] : 0.f;
        float s  = a + b2;
        float mx = hi ? fmaxf(a, b2) : a;
        float mn = hi ? fminf(a, b2) : a;
        #pragma unroll
        for (int o = 16; o; o >>= 1) {
            s  += __shfl_down_sync(0xffffffffu, s,  o);
            mx  = fmaxf(mx, __shfl_down_sync(0xffffffffu, mx, o));
            mn  = fminf(mn, __shfl_down_sync(0xffffffffu, mn, o));
        }
        if (tid == 0) {
            feat_out[b * FEAT + d]         = s * (1.0f / (float)NS);
            feat_out[b * FEAT + C + d]     = mx;
            feat_out[b * FEAT + 2 * C + d] = mn;
        }
    }

    // ---- phase 4c: horizontal interpolation table ----
    {
        float* hrows = (float*)hr4;
        for (int i = tid; i < POOL * W; i += NT) {
            const int r = i / W, j = i - r * W;
            const float sx = (j + 0.5f) * (1.0f / 32.0f) - 0.5f;
            const float x0f = floorf(sx);
            const float fx = sx - x0f;
            const int x0 = max(0, min(6, (int)x0f));
            const int x1 = max(0, min(6, (int)x0f + 1));
            const float a = g[r * POOL + x0];
            hrows[r * W + j] = a + fx * (g[r * POOL + x1] - a);
        }
    }
    __syncthreads();

    // ---- phase 4d: vertical pass + streaming stores ----
    if (tid < 448) {
        const int s  = tid / W4;         // 0..7 row segment
        const int c4 = tid - s * W4;     // 0..55
        const bool edge = (s == 0) | (s == 7);
        const int y0 = (s == 0) ? 0 : (s - 1);
        const int y1 = (s == 7) ? 6 : s;
        const int row0 = (s == 0) ? 0 : (32 * s - 16);
        const int n = edge ? 16 : 32;

        const float4 a  = hr4[y0 * W4 + c4];
        const float4 bb = hr4[y1 * W4 + c4];
        const float dxv = bb.x - a.x, dyv = bb.y - a.y;
        const float dzv = bb.z - a.z, dwv = bb.w - a.w;

        float4* __restrict__ o =
            (float4*)(out + (size_t)bc * HWSZ) + row0 * W4 + c4;
        #pragma unroll
        for (int r = 0; r < 32; ++r) {
            if (r < n) {
                const float fy = 0.015625f + (float)r * 0.03125f;
                float4 vv;
                vv.x = fmaf(fy, dxv, a.x);
                vv.y = fmaf(fy, dyv, a.y);
                vv.z = fmaf(fy, dzv, a.z);
                vv.w = fmaf(fy, dwv, a.w);
                __stcs(&o[r * W4], vv);
            }
        }
    }
}

// ---------------------------------------------------------------------------
extern "C" void kernel_launch(void* const* d_in, const int* in_sizes, int n_in,
                              void* d_out, int out_size)
{
    const float* x       = (const float*)d_in[0];   // (128,6,224,224) f32
    const float* P_delta = (const float*)d_in[1];   // (6,6) f32
    float* out = (float*)d_out;                     // [B*18 | B*C*H*W]

    const int PAD = 92 * 1024;    // pad -> ~101KB/block -> exactly 2 blocks/SM
    cudaFuncSetAttribute(fused_kernel,
                         cudaFuncAttributeMaxDynamicSharedMemorySize, PAD);

    fused_kernel<<<BC, NT, PAD>>>(x, P_delta, out, out + (size_t)B * FEAT);
}

// round 13
// speedup vs baseline: 1.0785x; 1.0785x over previous
#include <cuda_runtime.h>
#include <cuda_fp16.h>
#include <math.h>

#define B 128
#define C 6
#define H 224
#define W 224
#define HWSZ (H*W)          // 50176
#define HW4 (HWSZ/4)        // 12544 float4 per channel
#define HW2 (HWSZ/2)        // 25088 half2 per channel
#define POOL 7
#define NS (POOL*POOL)      // 49
#define BC (B*C)            // 768
#define CS (C*NS)           // 294
#define FEAT (3*C)          // 18
#define W4 (W/4)            // 56 float4 per row
#define WH2 (W/2)           // 112 half2 per row
#define NT 512

__device__ float g_pooled[BC * NS];
__device__ unsigned int g_cnt[B];    // monotonic ticket counters (never reset)

__constant__ float c_prior[36] = {
    1.0f,  0.0f,  0.6f,  0.0f, -2.0f, 0.0f,
    0.0f,  1.0f,  0.6f,  0.0f,  0.0f, 0.0f,
    0.1f,  0.1f,  0.5f,  0.0f,  0.0f, 0.0f,
    0.0f,  0.0f,  0.0f,  1.0f,  0.0f, 0.0f,
    0.0f,  0.0f,  0.0f,  0.0f,  1.0f, 0.2f,
    0.0f, -0.6f, -0.6f, -0.6f,  0.6f, 1.0f
};
__constant__ float c_sign[6] = {1.f, -1.f, 1.f, -1.f, 1.f, 1.f};

__device__ __forceinline__ float tanh_f(float x) {
    float y;
    asm("tanh.approx.f32 %0, %1;" : "=f"(y) : "f"(x));
    return y;
}
__device__ __forceinline__ unsigned h2u(__half2 h) { return *(unsigned*)&h; }

// ---------------------------------------------------------------------------
// Fully fused, single-DRAM-read kernel. Block = (batch b, concept d), 512 thr,
// 100KB fp16 shadow -> 2 blocks/SM.
//  1. stream own 200KB channel from DRAM ONCE: fp32 stats + fp16 smem shadow
//  2. gate (fp32 tanh) + 32x32 pool from smem (no L2/DRAM re-read)
//  3. ticket barrier per batch (monotonic counter, replay-safe, no reset)
//  4. mixing + features + bilinear upsample (writes overlap others' reads)
// Total DRAM traffic: 154MB read + 154MB write (was 462MB).
// ---------------------------------------------------------------------------
__global__ __launch_bounds__(NT, 2)
void fused_kernel(const float* __restrict__ x,
                  const float* __restrict__ P_delta,
                  float* __restrict__ feat_out,
                  float* __restrict__ out)
{
    extern __shared__ __align__(16) __half2 shadow[];   // 25088 half2 = 100352 B
    __shared__ float ra[16], rb[16];
    __shared__ float s_sc, s_of;
    __shared__ float xs[CS], sal[CS], tmp[NS];
    __shared__ float Pcol[C], smean[C];
    __shared__ __align__(16) float g[52];
    __shared__ __align__(16) float4 hr4[POOL * W4];

    const int bc = blockIdx.x;
    const int b = bc / C, d = bc - b * C;
    const int tid = threadIdx.x;
    const int warp = tid >> 5, lane = tid & 31;
    const float* __restrict__ xc = x + (size_t)bc * HWSZ;

    // ---- phase 1: single DRAM read -> stats + fp16 shadow ----
    {
        const float4* __restrict__ xin = (const float4*)xc;
        uint2* __restrict__ s64 = (uint2*)shadow;
        float sum = 0.f, sq = 0.f;
        #pragma unroll
        for (int base = 0; base < 24; base += 8) {
            float4 v[8];
            #pragma unroll
            for (int k = 0; k < 8; ++k) v[k] = xin[(base + k) * NT + tid];
            #pragma unroll
            for (int k = 0; k < 8; ++k) {
                sum += (v[k].x + v[k].y) + (v[k].z + v[k].w);
                sq  += fmaf(v[k].x, v[k].x, fmaf(v[k].y, v[k].y,
                       fmaf(v[k].z, v[k].z, v[k].w * v[k].w)));
                uint2 u;
                u.x = h2u(__floats2half2_rn(v[k].x, v[k].y));
                u.y = h2u(__floats2half2_rn(v[k].z, v[k].w));
                s64[(base + k) * NT + tid] = u;
            }
        }
        if (tid < HW4 - 24 * NT) {                 // tail: 256 float4
            float4 v = xin[24 * NT + tid];
            sum += (v.x + v.y) + (v.z + v.w);
            sq  += fmaf(v.x, v.x, fmaf(v.y, v.y, fmaf(v.z, v.z, v.w * v.w)));
            uint2 u;
            u.x = h2u(__floats2half2_rn(v.x, v.y));
            u.y = h2u(__floats2half2_rn(v.z, v.w));
            s64[24 * NT + tid] = u;
        }
        #pragma unroll
        for (int o = 16; o; o >>= 1) {
            sum += __shfl_down_sync(0xffffffffu, sum, o);
            sq  += __shfl_down_sync(0xffffffffu, sq,  o);
        }
        if (lane == 0) { ra[warp] = sum; rb[warp] = sq; }
        __syncthreads();                            // also fences shadow
        if (warp == 0) {
            float s = (lane < 16) ? ra[lane] : 0.f;
            float q = (lane < 16) ? rb[lane] : 0.f;
            #pragma unroll
            for (int o = 8; o; o >>= 1) {
                s += __shfl_down_sync(0xffffffffu, s, o);
                q += __shfl_down_sync(0xffffffffu, q, o);
            }
            if (lane == 0) {
                const float invN = 1.0f / (float)HWSZ;
                float mean = s * invN;
                float var = fmaxf((q - s * s * invN)
                                  * (1.0f / (float)(HWSZ - 1)), 0.f);
                float is = 1.0f / (sqrtf(var) + 1e-5f);
                s_sc = is; s_of = -mean * is;       // tanh arg = (x-m)/std
            }
        }
        __syncthreads();
    }
    const float sc = s_sc, of = s_of;

    // ---- phase 2: gate + pool from smem shadow ----
    {
        const int r2  = lane >> 4;       // 0..1 row parity in window
        const int c16 = lane & 15;       // half2 column in 32-wide window
        for (int win = warp; win < NS; win += 16) {
            const int py = win / POOL, px = win - py * POOL;
            const __half2* __restrict__ basep =
                shadow + (py * 32 + r2) * WH2 + px * 16 + c16;
            float acc = 0.f;
            #pragma unroll
            for (int rp = 0; rp < 16; ++rp) {       // rows r2, r2+2, ..., r2+30
                float2 f = __half22float2(basep[rp * 2 * WH2]);
                acc += tanh_f(fmaf(f.x, sc, of)) + tanh_f(fmaf(f.y, sc, of));
            }
            #pragma unroll
            for (int o = 16; o; o >>= 1)
                acc += __shfl_down_sync(0xffffffffu, acc, o);
            if (lane == 0)
                g_pooled[bc * NS + win] = acc * (1.0f / 2048.0f) + 0.5f;
        }
    }
    __syncthreads();

    // ---- phase 3: ticket barrier (replay-safe monotonic counter) ----
    if (tid == 0) {
        __threadfence();
        unsigned int ticket = atomicAdd(&g_cnt[b], 1u);
        unsigned int target = (ticket / C + 1u) * C;
        while (atomicAdd(&g_cnt[b], 0u) < target) __nanosleep(512);
    }
    __syncthreads();
    __threadfence();

    // ---- phase 4a: graph mixing ----
    if (tid < CS) xs[tid] = __ldcg(&g_pooled[b * CS + tid]);
    if (tid < C) Pcol[tid] = c_prior[tid * 6 + d] + 0.2f * tanhf(P_delta[tid * 6 + d]);
    __syncthreads();

    if (tid < C) {
        float m = 0.f;
        #pragma unroll
        for (int s = 0; s < NS; ++s) m += xs[tid * NS + s];
        smean[tid] = m * (1.0f / (float)NS);
    }
    __syncthreads();

    if (tid < CS) {
        const int cc = tid / NS;
        sal[tid] = fmaxf(c_sign[cc] * (xs[tid] - smean[cc]), 0.0f);
    }
    __syncthreads();

    if (tid < NS) {
        tmp[tid] = sal[tid]        * Pcol[0] + sal[NS + tid]   * Pcol[1]
                 + sal[2*NS + tid] * Pcol[2] + sal[3*NS + tid] * Pcol[3]
                 + sal[4*NS + tid] * Pcol[4] + sal[5*NS + tid] * Pcol[5];
    }
    __syncthreads();

    if (tid < NS) {
        const int ty = tid / POOL, tx = tid - ty * POOL;
        float acc = 0.f;
        int s = 0;
        #pragma unroll
        for (int sy = 0; sy < POOL; ++sy) {
            const float dy2 = (float)((sy - ty) * (sy - ty));
            #pragma unroll
            for (int sx = 0; sx < POOL; ++sx, ++s) {
                const float dx = (float)(sx - tx);
                acc += __expf(-(dy2 + dx * dx) * 0.78125f) * tmp[s];
            }
        }
        g[tid] = c_sign[d] * fmaxf(acc, 0.0f);
    }
    __syncthreads();

    // ---- phase 4b: features ----
    if (tid < 32) {
        float a  = g[tid];
        bool hi  = (tid + 32) < NS;
        float b2 = hi ? g[tid + 32] : 0.f;
        float s  = a + b2;
        float mx = hi ? fmaxf(a, b2) : a;
        float mn = hi ? fminf(a, b2) : a;
        #pragma unroll
        for (int o = 16; o; o >>= 1) {
            s  += __shfl_down_sync(0xffffffffu, s,  o);
            mx  = fmaxf(mx, __shfl_down_sync(0xffffffffu, mx, o));
            mn  = fminf(mn, __shfl_down_sync(0xffffffffu, mn, o));
        }
        if (tid == 0) {
            feat_out[b * FEAT + d]         = s * (1.0f / (float)NS);
            feat_out[b * FEAT + C + d]     = mx;
            feat_out[b * FEAT + 2 * C + d] = mn;
        }
    }

    // ---- phase 4c: horizontal interpolation table ----
    {
        float* hrows = (float*)hr4;
        for (int i = tid; i < POOL * W; i += NT) {
            const int r = i / W, j = i - r * W;
            const float sx = (j + 0.5f) * (1.0f / 32.0f) - 0.5f;
            const float x0f = floorf(sx);
            const float fx = sx - x0f;
            const int x0 = max(0, min(6, (int)x0f));
            const int x1 = max(0, min(6, (int)x0f + 1));
            const float a = g[r * POOL + x0];
            hrows[r * W + j] = a + fx * (g[r * POOL + x1] - a);
        }
    }
    __syncthreads();

    // ---- phase 4d: vertical pass + streaming stores ----
    if (tid < 448) {
        const int s  = tid / W4;         // 0..7 row segment
        const int c4 = tid - s * W4;     // 0..55
        const bool edge = (s == 0) | (s == 7);
        const int y0 = (s == 0) ? 0 : (s - 1);
        const int y1 = (s == 7) ? 6 : s;
        const int row0 = (s == 0) ? 0 : (32 * s - 16);
        const int n = edge ? 16 : 32;

        const float4 a  = hr4[y0 * W4 + c4];
        const float4 bb = hr4[y1 * W4 + c4];
        const float dxv = bb.x - a.x, dyv = bb.y - a.y;
        const float dzv = bb.z - a.z, dwv = bb.w - a.w;

        float4* __restrict__ o =
            (float4*)(out + (size_t)bc * HWSZ) + row0 * W4 + c4;
        #pragma unroll
        for (int r = 0; r < 32; ++r) {
            if (r < n) {
                const float fy = 0.015625f + (float)r * 0.03125f;
                float4 vv;
                vv.x = fmaf(fy, dxv, a.x);
                vv.y = fmaf(fy, dyv, a.y);
                vv.z = fmaf(fy, dzv, a.z);
                vv.w = fmaf(fy, dwv, a.w);
                __stcs(&o[r * W4], vv);
            }
        }
    }
}

// ---------------------------------------------------------------------------
extern "C" void kernel_launch(void* const* d_in, const int* in_sizes, int n_in,
                              void* d_out, int out_size)
{
    const float* x       = (const float*)d_in[0];   // (128,6,224,224) f32
    const float* P_delta = (const float*)d_in[1];   // (6,6) f32
    float* out = (float*)d_out;                     // [B*18 | B*C*H*W]

    const int SMEM = HW2 * 4;    // 100352 B fp16 shadow
    cudaFuncSetAttribute(fused_kernel,
                         cudaFuncAttributeMaxDynamicSharedMemorySize, SMEM);

    fused_kernel<<<BC, NT, SMEM>>>(x, P_delta, out, out + (size_t)B * FEAT);
}